// round 17
// baseline (speedup 1.0000x reference)
#include <cuda_runtime.h>
#include <cuda_bf16.h>
#include <math.h>
#include <stdint.h>

// ---------------- problem constants ----------------
#define BATCH 64
#define SEQ   64
#define EMB   256
#define UNITS 512
#define GRU   256
#define FC    1024
#define VOCAB 50000

// ---------------- scratch (device globals; no allocation allowed) ----------------
__device__ float g_hidproj[BATCH * UNITS];
__device__ float g_qp[BATCH * SEQ * UNITS];
__device__ float g_score[BATCH * SEQ];
__device__ float g_gx[BATCH * 2 * EMB];
__device__ float g_fcin[BATCH * (GRU + UNITS)];
__device__ float g_t1[BATCH * FC];
__device__ float g_t2[BATCH * FC];
__device__ float g_part[8 * BATCH * FC];
__device__ float g_qsdup[EMB * 2 * (BATCH * SEQ)];   // qs dup2 layout: [K/2][4M]
__device__ float g_t2dup[FC * 2 * BATCH];            // t2 dup2 layout: [K/2][4M]

// ---------------- packed dual-fp32 FMA (B300 FFMA2) ----------------
__device__ __forceinline__ uint64_t ffma2(uint64_t a, uint64_t b, uint64_t c) {
    uint64_t d;
    asm("fma.rn.f32x2 %0, %1, %2, %3;" : "=l"(d) : "l"(a), "l"(b), "l"(c));
    return d;
}
__device__ __forceinline__ uint64_t dup2(float x) {
    uint64_t d; uint32_t u = __float_as_uint(x);
    asm("mov.b64 %0, {%1, %1};" : "=l"(d) : "r"(u));
    return d;
}
__device__ __forceinline__ uint32_t smem_u32(const void* p) {
    uint32_t a;
    asm("{ .reg .u64 t; cvta.to.shared.u64 t, %1; cvt.u32.u64 %0, t; }" : "=r"(a) : "l"(p));
    return a;
}
// sm_90 baseline bulk copy: global -> shared, completion via mbarrier tx-bytes
__device__ __forceinline__ void bulk_cp(uint32_t dst, const void* src,
                                        uint32_t bytes, uint32_t mbar) {
    asm volatile(
        "cp.async.bulk.shared::cluster.global.mbarrier::complete_tx::bytes [%0], [%1], %2, [%3];"
        :: "r"(dst), "l"(src), "r"(bytes), "r"(mbar) : "memory");
}
#define MBARRIER_INIT(mb, c) \
    asm volatile("mbarrier.init.shared.b64 [%0], %1;" :: "r"((uint32_t)(mb)), "r"((uint32_t)(c)) : "memory")
#define MBARRIER_EXPECT_TX(mb, tx) \
    asm volatile("mbarrier.arrive.expect_tx.shared.b64 _, [%0], %1;" :: "r"((uint32_t)(mb)), "r"((uint32_t)(tx)) : "memory")
#define MBARRIER_WAIT_PARITY(mb, ph) do { \
    uint32_t _mb = (uint32_t)(mb), _ph = (uint32_t)(ph), _done; \
    asm volatile("{\n\t.reg .pred p;\n\tmbarrier.try_wait.parity.acquire.cta.shared::cta.b64 p, [%1], %2;\n\tselp.b32 %0, 1, 0, p;\n\t}" \
        : "=r"(_done) : "r"(_mb), "r"(_ph) : "memory"); \
    if (!_done) { \
        asm volatile("{\n\t.reg .pred P1;\n\tWL_%=:\n\tmbarrier.try_wait.parity.acquire.cta.shared::cta.b64 P1, [%0], %1, 0x989680;\n\t@P1 bra.uni WD_%=;\n\tbra.uni WL_%=;\n\tWD_%=:\n\t}" \
            :: "r"(_mb), "r"(_ph) : "memory"); \
    } \
} while (0)

// ---------------- dup_k2: Adup[k/2][4m + 2(k&1) + {0,1}] = A[m][k] ----------------
__global__ __launch_bounds__(256) void dup_k2(
    const float* __restrict__ A, float* __restrict__ Adup, int M, int K)
{
    __shared__ float tile[32][33];
    const int tx = threadIdx.x & 31, ty = threadIdx.x >> 5;
    const int k0 = blockIdx.x * 32, m0 = blockIdx.y * 32;
#pragma unroll
    for (int r = 0; r < 4; r++)
        tile[ty + 8 * r][tx] = A[(size_t)(m0 + ty + 8 * r) * K + k0 + tx];
    __syncthreads();
    const size_t M4 = 4 * (size_t)M;
#pragma unroll
    for (int r = 0; r < 4; r++) {
        int kk = ty + 8 * r;
        float v = tile[tx][kk];
        size_t off = (size_t)((k0 + kk) >> 1) * M4 + 4 * (m0 + tx) + 2 * (kk & 1);
        *(float2*)&Adup[off] = make_float2(v, v);
    }
}

// ================= gemm_blk: FFMA2 GEMM, bulk-copy 3-stage ring =================
// C[M,N] = A[M,K] @ B[K,N] + bias, A in dup2 layout [K/2][4M].
// CTA tile 64x128, 128 threads, thread tile 8m x 8n (cols 8tx..8tx+7).
// Staging: one thread issues cp.async.bulk row copies; mbarrier tx completion.
// Requires M%64==0, K%32==0 (NT>=2), N%8==0.
#define GB_APITCH 264                        // floats per A k2-row (1056B)
#define GB_ABUF   (16 * GB_APITCH)           // 4224 floats
#define GB_BBUF   (32 * 128)                 // 4096 floats
#define GB_STG    (GB_ABUF + GB_BBUF)        // 8320 floats per stage
#define GB_HDR    32                         // floats (mbarrier header)
#define GB_SMEM   ((GB_HDR + 3 * GB_STG) * 4)   // 99968 bytes

__global__ __launch_bounds__(128) void gemm_blk(
    const float* __restrict__ Adup, const float* __restrict__ B,
    const float* __restrict__ bias, float* __restrict__ C,
    int M, int N, int K)
{
    extern __shared__ float sm[];
    const uint32_t sbase = smem_u32(sm);

    const int tid = threadIdx.x, tx = tid & 15, ty = tid >> 4;
    const int n0 = blockIdx.x * 128, m0 = blockIdx.y * 64;
    const int NT = K >> 5;
    const size_t M4 = 4 * (size_t)M;
    const uint32_t brow = (uint32_t)((N - n0 < 128 ? N - n0 : 128) * 4);  // B row bytes
    const uint32_t txbytes = 16 * 1024 + 32 * brow;

    if (tid == 0) {
        MBARRIER_INIT(sbase + 0, 1);
        MBARRIER_INIT(sbase + 8, 1);
        MBARRIER_INIT(sbase + 16, 1);
    }
    __syncthreads();

    auto stage = [&](int s, int u) {
        const uint32_t sA = sbase + (GB_HDR + u * GB_STG) * 4;
        const uint32_t sB = sA + GB_ABUF * 4;
        const uint32_t mb = sbase + u * 8;
        MBARRIER_EXPECT_TX(mb, txbytes);
        const float* asrc = Adup + (size_t)(s * 16) * M4 + 4 * m0;
#pragma unroll 4
        for (int r = 0; r < 16; r++)
            bulk_cp(sA + r * (GB_APITCH * 4), asrc + (size_t)r * M4, 1024u, mb);
        const float* bsrc = B + (size_t)(s * 32) * N + n0;
#pragma unroll 4
        for (int r = 0; r < 32; r++)
            bulk_cp(sB + r * 512, bsrc + (size_t)r * N, brow, mb);
    };

    if (tid == 0) {
        stage(0, 0);
        if (NT > 1) stage(1, 1);
    }

    uint64_t acc[8][4];
#pragma unroll
    for (int i = 0; i < 8; i++)
#pragma unroll
        for (int j = 0; j < 4; j++) acc[i][j] = 0ull;

    for (int s = 0; s < NT; s++) {
        const int u = s % 3;
        MBARRIER_WAIT_PARITY(sbase + u * 8, (s / 3) & 1);

        const float* Ab = sm + GB_HDR + u * GB_STG + 4 * ty;
        const float* Bb = sm + GB_HDR + u * GB_STG + GB_ABUF + 8 * tx;
#pragma unroll
        for (int k2 = 0; k2 < 16; k2++) {
            ulonglong2 be0 = *(const ulonglong2*)(Bb + (2 * k2) * 128);
            ulonglong2 be1 = *(const ulonglong2*)(Bb + (2 * k2) * 128 + 4);
            ulonglong2 bo0 = *(const ulonglong2*)(Bb + (2 * k2 + 1) * 128);
            ulonglong2 bo1 = *(const ulonglong2*)(Bb + (2 * k2 + 1) * 128 + 4);
            const float* arow = Ab + k2 * GB_APITCH;
#pragma unroll
            for (int i = 0; i < 8; i++) {
                ulonglong2 av = *(const ulonglong2*)(arow + 32 * i);  // {even pair, odd pair}
                acc[i][0] = ffma2(av.x, be0.x, acc[i][0]);
                acc[i][1] = ffma2(av.x, be0.y, acc[i][1]);
                acc[i][2] = ffma2(av.x, be1.x, acc[i][2]);
                acc[i][3] = ffma2(av.x, be1.y, acc[i][3]);
                acc[i][0] = ffma2(av.y, bo0.x, acc[i][0]);
                acc[i][1] = ffma2(av.y, bo0.y, acc[i][1]);
                acc[i][2] = ffma2(av.y, bo1.x, acc[i][2]);
                acc[i][3] = ffma2(av.y, bo1.y, acc[i][3]);
            }
        }
        __syncthreads();                         // all warps done with slot (s+2)%3's old use
        if (s + 2 < NT && tid == 0) stage(s + 2, (s + 2) % 3);
    }

    // ---- epilogue: two STG.128 per row (N % 8 == 0 for all uses) ----
    const int n = n0 + 8 * tx;
    if (n < N) {
        float4 bv0 = *(const float4*)&bias[n];
        float4 bv1 = *(const float4*)&bias[n + 4];
#pragma unroll
        for (int i = 0; i < 8; i++) {
            int m = m0 + ty + 8 * i;
            float2 p0 = *(float2*)&acc[i][0];
            float2 p1 = *(float2*)&acc[i][1];
            float2 p2 = *(float2*)&acc[i][2];
            float2 p3 = *(float2*)&acc[i][3];
            float4 o0 = make_float4(p0.x + bv0.x, p0.y + bv0.y, p1.x + bv0.z, p1.y + bv0.w);
            float4 o1 = make_float4(p2.x + bv1.x, p2.y + bv1.y, p3.x + bv1.z, p3.y + bv1.w);
            *(float4*)&C[(size_t)m * N + n] = o0;
            *(float4*)&C[(size_t)m * N + n + 4] = o1;
        }
    }
}

// ================= dense8_ks: batch-tiled (8) + K-split(8) dense partials ==========
__global__ __launch_bounds__(256) void dense8_ks(
    const float* __restrict__ in, const float* __restrict__ W,
    float* __restrict__ part, int IN, int OUT, int KC)
{
    extern __shared__ float ins[];
    const int o = blockIdx.x * 256 + threadIdx.x;
    const int bg = blockIdx.y * 8;
    const int kbase = blockIdx.z * KC;

#pragma unroll
    for (int bb = 0; bb < 8; bb++)
        for (int k = threadIdx.x; k < KC; k += 256)
            ins[k * 10 + bb] = in[(bg + bb) * IN + kbase + k];
    __syncthreads();

    uint64_t acc[4] = {0ull, 0ull, 0ull, 0ull};
    const float* Wp = W + (size_t)kbase * OUT + o;
#pragma unroll 8
    for (int k = 0; k < KC; k++) {
        uint64_t ww = dup2(Wp[(size_t)k * OUT]);
        const uint64_t* ip = (const uint64_t*)&ins[k * 10];
        acc[0] = ffma2(ww, ip[0], acc[0]);
        acc[1] = ffma2(ww, ip[1], acc[1]);
        acc[2] = ffma2(ww, ip[2], acc[2]);
        acc[3] = ffma2(ww, ip[3], acc[3]);
    }
    float* pp = part + ((size_t)blockIdx.z * BATCH + bg) * OUT + o;
#pragma unroll
    for (int j = 0; j < 4; j++) {
        float2 p = *(float2*)&acc[j];
        pp[(2 * j) * OUT] = p.x;
        pp[(2 * j + 1) * OUT] = p.y;
    }
}

// ---------------- finisher ----------------
__global__ __launch_bounds__(256) void fin_k(
    const float* __restrict__ part, const float* __restrict__ bias,
    float* __restrict__ out, int OUT, int KS)
{
    int i = blockIdx.x * 256 + threadIdx.x;
    float s = bias[i % OUT];
    for (int c = 0; c < KS; c++) s += part[c * BATCH * OUT + i];
    out[i] = s;
}

// ---------------- GRU finisher (h0 = 0) ----------------
__global__ __launch_bounds__(256) void gru_fin(
    const float* __restrict__ part, const float* __restrict__ bg,
    const float* __restrict__ features,
    float* __restrict__ state_out, float* __restrict__ fc_in)
{
    const int b = blockIdx.x, g = threadIdx.x;
    float mz = 0.f, mr = 0.f, mh = 0.f;
#pragma unroll
    for (int c = 0; c < 8; c++) {
        const float* p = part + (c * BATCH + b) * (3 * GRU);
        mz += p[g]; mr += p[GRU + g]; mh += p[2 * GRU + g];
    }
    mz += bg[g]; mr += bg[GRU + g]; mh += bg[2 * GRU + g];
    const float* bgh = bg + 3 * GRU;
    float z = 1.f / (1.f + expf(-(mz + bgh[g])));
    float r = 1.f / (1.f + expf(-(mr + bgh[GRU + g])));
    float hc = tanhf(mh + r * bgh[2 * GRU + g]);
    float st = (1.f - z) * hc;
    state_out[b * GRU + g] = st;
    fc_in[b * (GRU + UNITS) + g] = st;
    fc_in[b * (GRU + UNITS) + GRU + g] = features[b * UNITS + g];
    fc_in[b * (GRU + UNITS) + GRU + 256 + g] = features[b * UNITS + 256 + g];
}

// ---------------- attention score ----------------
__global__ __launch_bounds__(256) void score_k(
    const float* __restrict__ qp, const float* __restrict__ hidproj,
    const float* __restrict__ V, const float* __restrict__ bV,
    float* __restrict__ score)
{
    int bs = blockIdx.x, b = bs >> 6, t = threadIdx.x;
    const float* qrow = qp + bs * UNITS;
    const float* hp = hidproj + b * UNITS;
    float s = 0.f;
    for (int u = t; u < UNITS; u += 256)
        s += tanhf(qrow[u] + hp[u]) * V[u];
    __shared__ float red[256];
    red[t] = s; __syncthreads();
    for (int o = 128; o > 0; o >>= 1) {
        if (t < o) red[t] += red[t + o];
        __syncthreads();
    }
    if (t == 0) score[bs] = red[0] + bV[0];
}

// ---------------- softmax + context + embedding ----------------
__global__ __launch_bounds__(64) void softctx_k(
    const float* __restrict__ score, const float* __restrict__ qs,
    const int* __restrict__ x, const float* __restrict__ E,
    float* __restrict__ weights_out, float* __restrict__ gx)
{
    int b = blockIdx.y, part = blockIdx.x, t = threadIdx.x;
    __shared__ float w[SEQ];
    w[t] = score[b * SEQ + t];
    __syncthreads();
    if (t < 32) {
        float a0 = w[t], a1 = w[t + 32];
        float m = fmaxf(a0, a1);
#pragma unroll
        for (int o = 16; o; o >>= 1) m = fmaxf(m, __shfl_xor_sync(0xffffffff, m, o));
        float e0 = expf(a0 - m), e1 = expf(a1 - m);
        float s = e0 + e1;
#pragma unroll
        for (int o = 16; o; o >>= 1) s += __shfl_xor_sync(0xffffffff, s, o);
        float inv = 1.f / s;
        w[t] = e0 * inv; w[t + 32] = e1 * inv;
    }
    __syncthreads();
    if (part == 0) weights_out[b * SEQ + t] = w[t];
    int e = part * 64 + t;
    float c = 0.f;
#pragma unroll 8
    for (int s2 = 0; s2 < SEQ; s2++)
        c = fmaf(w[s2], qs[(b * SEQ + s2) * EMB + e], c);
    gx[b * 2 * EMB + EMB + e] = c;
    gx[b * 2 * EMB + e] = E[x[b] * EMB + e];
}

// ---------------- launch ----------------
extern "C" void kernel_launch(void* const* d_in, const int* in_sizes, int n_in,
                              void* d_out, int out_size)
{
    const int*   x        = (const int*)  d_in[0];
    const float* qs       = (const float*)d_in[1];
    const float* features = (const float*)d_in[2];
    const float* hidden   = (const float*)d_in[3];
    const float* E        = (const float*)d_in[4];
    const float* W1       = (const float*)d_in[5];
    const float* b1       = (const float*)d_in[6];
    const float* W2       = (const float*)d_in[7];
    const float* b2       = (const float*)d_in[8];
    const float* V        = (const float*)d_in[9];
    const float* bV       = (const float*)d_in[10];
    const float* Kg       = (const float*)d_in[11];
    /* d_in[12] = Ug dead (h0 == 0) */
    const float* bg       = (const float*)d_in[13];
    const float* Wf1      = (const float*)d_in[14];
    const float* bf1      = (const float*)d_in[15];
    const float* Wf2      = (const float*)d_in[16];
    const float* bf2      = (const float*)d_in[17];
    const float* Wo       = (const float*)d_in[18];
    const float* bo       = (const float*)d_in[19];

    float* out = (float*)d_out;
    float* logits      = out;
    float* state_out   = out + BATCH * VOCAB;
    float* weights_out = state_out + BATCH * GRU;

    float *hidproj, *qp, *score, *gx, *fcin, *t1, *t2, *part, *qsdup, *t2dup;
    cudaGetSymbolAddress((void**)&hidproj, g_hidproj);
    cudaGetSymbolAddress((void**)&qp,      g_qp);
    cudaGetSymbolAddress((void**)&score,   g_score);
    cudaGetSymbolAddress((void**)&gx,      g_gx);
    cudaGetSymbolAddress((void**)&fcin,    g_fcin);
    cudaGetSymbolAddress((void**)&t1,      g_t1);
    cudaGetSymbolAddress((void**)&t2,      g_t2);
    cudaGetSymbolAddress((void**)&part,    g_part);
    cudaGetSymbolAddress((void**)&qsdup,   g_qsdup);
    cudaGetSymbolAddress((void**)&t2dup,   g_t2dup);

    cudaFuncSetAttribute(gemm_blk, cudaFuncAttributeMaxDynamicSharedMemorySize, GB_SMEM);

    // 1-2: hidden @ W2 + b2  (K-split 8 -> 128 blocks)
    dense8_ks<<<dim3(UNITS / 256, BATCH / 8, 8), 256, 64 * 10 * 4>>>(
        hidden, W2, part, UNITS, UNITS, 64);
    fin_k<<<BATCH * UNITS / 256, 256>>>(part, b2, hidproj, UNITS, 8);
    // 3: dup2-transpose qs  [4096,256] -> [128][16384]
    dup_k2<<<dim3(EMB / 32, (BATCH * SEQ) / 32), 256>>>(qs, qsdup, BATCH * SEQ, EMB);
    // 4 (PROFILED): qs @ W1 + b1  (256 CTAs, single wave at 2/SM)
    gemm_blk<<<dim3(UNITS / 128, (BATCH * SEQ) / 64), 128, GB_SMEM>>>(
        qsdup, W1, b1, qp, BATCH * SEQ, UNITS, EMB);
    // 5-6: score + softmax/context/embed
    score_k<<<BATCH * SEQ, 256>>>(qp, hidproj, V, bV, score);
    softctx_k<<<dim3(4, BATCH), 64>>>(score, qs, x, E, weights_out, gx);
    // 7-8: GRU (K-split 8 -> 192 blocks)
    dense8_ks<<<dim3(3 * GRU / 256, BATCH / 8, 8), 256, 64 * 10 * 4>>>(
        gx, Kg, part, 2 * EMB, 3 * GRU, 64);
    gru_fin<<<BATCH, GRU>>>(part, bg, features, state_out, fcin);
    // 9-12: fc stack (K-split 8 -> 256 blocks each)
    dense8_ks<<<dim3(FC / 256, BATCH / 8, 8), 256, 96 * 10 * 4>>>(
        fcin, Wf1, part, GRU + UNITS, FC, 96);
    fin_k<<<BATCH * FC / 256, 256>>>(part, bf1, t1, FC, 8);
    dense8_ks<<<dim3(FC / 256, BATCH / 8, 8), 256, 128 * 10 * 4>>>(
        t1, Wf2, part, FC, FC, 128);
    fin_k<<<BATCH * FC / 256, 256>>>(part, bf2, t2, FC, 8);
    // 13: dup2-transpose t2  [64,1024] -> [512][256]
    dup_k2<<<dim3(FC / 32, BATCH / 32), 256>>>(t2, t2dup, BATCH, FC);
    // 14: logits GEMM  [64,50000] = t2 @ Wo + bo  (391 n-tiles of 128 cols)
    gemm_blk<<<dim3((VOCAB + 127) / 128, 1), 128, GB_SMEM>>>(
        t2dup, Wo, bo, logits, BATCH, VOCAB, FC);
}